// round 1
// baseline (speedup 1.0000x reference)
#include <cuda_runtime.h>

// RNN_438086664357: h_{t+1} = tanh(W [h_t ; x_t] + b)
// out (T+1, B, DH) fp32; out[t] doubles as the hidden state for step t.
// Round 1: fp32 SIMT GEMM with packed fma.rn.f32x2, 257 kernel launches in graph.

#define TSTEPS 256
#define BATCH  256
#define DH     1024
#define KTOT   2048      // d_in + d_h

#define BM 32
#define BN 64
#define BK 32
#define BKP 34           // padded smem K-stride (float2-aligned, spreads banks)
#define NCHUNK (KTOT/BK) // 64
#define HCHUNK (DH/BK)   // 32 chunks come from h, rest from x

typedef unsigned long long u64;

__global__ void rnn_zero(float* __restrict__ out) {
    out[blockIdx.x * blockDim.x + threadIdx.x] = 0.0f;
}

__device__ __forceinline__ void ffma2(u64& d, u64 a, u64 b) {
    // packed f32x2 FMA (Blackwell): d.lo += a.lo*b.lo ; d.hi += a.hi*b.hi
    asm("fma.rn.f32x2 %0, %1, %2, %0;" : "+l"(d) : "l"(a), "l"(b));
}

__global__ void __launch_bounds__(128)
rnn_step(const float* __restrict__ hprev,   // (B, DH)   = out slice t
         const float* __restrict__ x,       // (B, DIN)  = seq slice t
         const float* __restrict__ W,       // (DH, KTOT) row-major
         const float* __restrict__ bias,    // (DH,)
         float* __restrict__ out)           // (B, DH)   = out slice t+1
{
    __shared__ __align__(16) float As[BM * BKP];
    __shared__ __align__(16) float Bs[BN * BKP];

    const int tid = threadIdx.x;
    const int tx  = tid & 15;     // 16 col-groups of 4
    const int ty  = tid >> 4;     // 8 row-groups of 4
    const int m0  = blockIdx.y * BM;
    const int n0  = blockIdx.x * BN;

    u64 acc[16];
    #pragma unroll
    for (int i = 0; i < 16; i++) acc[i] = 0ull;

    float4 ra[2], rb[4];

    // prefetch chunk 0 (always from hprev)
    #pragma unroll
    for (int u = 0; u < 2; u++) {
        int id = tid + u * 128;
        int r = id >> 3, c4 = id & 7;
        ra[u] = *(const float4*)(hprev + (m0 + r) * DH + c4 * 4);
    }
    #pragma unroll
    for (int u = 0; u < 4; u++) {
        int id = tid + u * 128;
        int r = id >> 3, c4 = id & 7;
        rb[u] = *(const float4*)(W + (n0 + r) * KTOT + c4 * 4);
    }

    for (int c = 0; c < NCHUNK; c++) {
        // regs -> smem (A: [m][k], B: [n][k], stride BKP)
        #pragma unroll
        for (int u = 0; u < 2; u++) {
            int id = tid + u * 128;
            int r = id >> 3, c4 = id & 7;
            float2* p = (float2*)&As[r * BKP + c4 * 4];
            p[0] = make_float2(ra[u].x, ra[u].y);
            p[1] = make_float2(ra[u].z, ra[u].w);
        }
        #pragma unroll
        for (int u = 0; u < 4; u++) {
            int id = tid + u * 128;
            int r = id >> 3, c4 = id & 7;
            float2* p = (float2*)&Bs[r * BKP + c4 * 4];
            p[0] = make_float2(rb[u].x, rb[u].y);
            p[1] = make_float2(rb[u].z, rb[u].w);
        }
        __syncthreads();

        // prefetch next chunk while computing this one
        if (c + 1 < NCHUNK) {
            const int cn = c + 1;
            const float* srcA = (cn < HCHUNK) ? hprev : x;
            const int kofA = (cn & (HCHUNK - 1)) * BK;
            const int kofW = cn * BK;
            #pragma unroll
            for (int u = 0; u < 2; u++) {
                int id = tid + u * 128;
                int r = id >> 3, c4 = id & 7;
                ra[u] = *(const float4*)(srcA + (m0 + r) * DH + kofA + c4 * 4);
            }
            #pragma unroll
            for (int u = 0; u < 4; u++) {
                int id = tid + u * 128;
                int r = id >> 3, c4 = id & 7;
                rb[u] = *(const float4*)(W + (n0 + r) * KTOT + kofW + c4 * 4);
            }
        }

        // compute: 16 k-pairs, 4x4 per-thread tile, packed along k
        #pragma unroll
        for (int kp = 0; kp < BK / 2; kp++) {
            const int k = kp * 2;
            u64 a2[4], b2[4];
            #pragma unroll
            for (int i = 0; i < 4; i++)
                a2[i] = *(const u64*)&As[(ty * 4 + i) * BKP + k];
            #pragma unroll
            for (int j = 0; j < 4; j++)
                b2[j] = *(const u64*)&Bs[(tx * 4 + j) * BKP + k];
            #pragma unroll
            for (int i = 0; i < 4; i++)
                #pragma unroll
                for (int j = 0; j < 4; j++)
                    ffma2(acc[i * 4 + j], a2[i], b2[j]);
        }
        __syncthreads();
    }

    // epilogue: fold hi/lo, add bias, tanh via exp (fast-math-safe precision)
    #pragma unroll
    for (int i = 0; i < 4; i++) {
        const int m = m0 + ty * 4 + i;
        float* orow = out + m * DH + n0;
        #pragma unroll
        for (int j = 0; j < 4; j++) {
            const u64 v = acc[i * 4 + j];
            const float lo = __uint_as_float((unsigned int)v);
            const float hi = __uint_as_float((unsigned int)(v >> 32));
            const int n = tx * 4 + j;
            const float z = lo + hi + bias[n0 + n];
            const float e = __expf(2.0f * z);       // rel err ~1e-6, safe
            orow[n] = 1.0f - 2.0f / (e + 1.0f);     // = tanh(z), handles +/-inf
        }
    }
}

extern "C" void kernel_launch(void* const* d_in, const int* in_sizes, int n_in,
                              void* d_out, int out_size) {
    const float* seq = (const float*)d_in[0];  // (T, B, DIN)
    const float* W   = (const float*)d_in[1];  // (DH, KTOT)
    const float* b   = (const float*)d_in[2];  // (DH,)
    float* out = (float*)d_out;                // (T+1, B, DH)

    (void)in_sizes; (void)n_in; (void)out_size;

    const int slice = BATCH * DH;              // 262144 elements per time slice

    // h_0 = 0 (d_out is poisoned)
    rnn_zero<<<slice / 256, 256>>>(out);

    dim3 grid(DH / BN, BATCH / BM);            // (16, 8) = 128 CTAs
    for (int t = 0; t < TSTEPS; t++) {
        rnn_step<<<grid, 128>>>(out + (size_t)t * slice,
                                seq + (size_t)t * slice,
                                W, b,
                                out + (size_t)(t + 1) * slice);
    }
}

// round 3
// speedup vs baseline: 5.1031x; 5.1031x over previous
#include <cuda_runtime.h>
#include <cuda_bf16.h>
#include <cstdint>

// RNN_438086664357: h_{t+1} = tanh(W [h_t ; x_t] + b)
// Round 3: mma.sync (HMMA) bf16 split-precision (3 products), cp.async pipeline.
// (tcgen05 unusable: harness PTX target is plain sm_103.)

#define TSTEPS 256
#define BATCH  256
#define DH     1024
#define DIN    1024
#define KTOT   2048
#define BM     32
#define BN     64
#define KC     64              // K elems per chunk (128B rows)
#define NCH    (KTOT / KC)     // 32
#define S      4               // pipeline stages

// stage layout (bytes): Ahi 4K | Alo 4K | Whi 8K | Wlo 8K
#define OFF_AHI 0
#define OFF_ALO 4096
#define OFF_WHI 8192
#define OFF_WLO 16384
#define STG     24576
#define SMEM_BYTES (S * STG)   // 98304

typedef unsigned int u32;

// ---- device scratch (__device__ globals: allocation-free rule) ----
__device__ __nv_bfloat16 g_xhi[(size_t)TSTEPS * BATCH * DIN];
__device__ __nv_bfloat16 g_xlo[(size_t)TSTEPS * BATCH * DIN];
__device__ __nv_bfloat16 g_whi[(size_t)DH * KTOT];
__device__ __nv_bfloat16 g_wlo[(size_t)DH * KTOT];
__device__ __nv_bfloat16 g_hhi[2 * (size_t)BATCH * DH];
__device__ __nv_bfloat16 g_hlo[2 * (size_t)BATCH * DH];

__device__ __forceinline__ u32 s2u(const void* p) {
    u32 a;
    asm("{ .reg .u64 t; cvta.to.shared.u64 t, %1; cvt.u32.u64 %0, t; }"
        : "=r"(a) : "l"(p));
    return a;
}

#define CP16(sm, gp) asm volatile("cp.async.cg.shared.global [%0], [%1], 16;" :: "r"(sm), "l"(gp))
#define CP_COMMIT()  asm volatile("cp.async.commit_group;" ::: "memory")

__device__ __forceinline__ void ldsm4(u32 a, u32& r0, u32& r1, u32& r2, u32& r3) {
    asm volatile("ldmatrix.sync.aligned.m8n8.x4.shared.b16 {%0,%1,%2,%3}, [%4];"
                 : "=r"(r0), "=r"(r1), "=r"(r2), "=r"(r3) : "r"(a));
}

__device__ __forceinline__ void mma16816(float* c, const u32* a, u32 b0, u32 b1) {
    asm volatile(
        "mma.sync.aligned.m16n8k16.row.col.f32.bf16.bf16.f32 "
        "{%0,%1,%2,%3}, {%4,%5,%6,%7}, {%8,%9}, {%0,%1,%2,%3};"
        : "+f"(c[0]), "+f"(c[1]), "+f"(c[2]), "+f"(c[3])
        : "r"(a[0]), "r"(a[1]), "r"(a[2]), "r"(a[3]), "r"(b0), "r"(b1));
}

// ---- setup kernels ----
__global__ void split_w(const float* __restrict__ W) {
    int i = blockIdx.x * blockDim.x + threadIdx.x;
    float v = W[i];
    __nv_bfloat16 h = __float2bfloat16(v);
    g_whi[i] = h;
    g_wlo[i] = __float2bfloat16(v - __bfloat162float(h));
}

__global__ void split_x(const float* __restrict__ X) {
    size_t i = (size_t)blockIdx.x * blockDim.x + threadIdx.x;
    float v = X[i];
    __nv_bfloat16 h = __float2bfloat16(v);
    g_xhi[i] = h;
    g_xlo[i] = __float2bfloat16(v - __bfloat162float(h));
}

__global__ void init_h(float* __restrict__ out0) {
    int i = blockIdx.x * blockDim.x + threadIdx.x;
    out0[i] = 0.0f;
    __nv_bfloat16 z = __float2bfloat16(0.0f);
    g_hhi[i] = z;  g_hlo[i] = z;
    g_hhi[BATCH * DH + i] = z;  g_hlo[BATCH * DH + i] = z;
}

// ---- per-step GEMM + tanh + split ----
__global__ void __launch_bounds__(128, 1)
rnn_step(const float* __restrict__ bias, float* __restrict__ outNext,
         int t, int parity)
{
    extern __shared__ char smem[];
    const u32 sb = s2u(smem);
    const int tid  = threadIdx.x;
    const int wid  = tid >> 5, lane = tid & 31;
    const int wm   = wid & 1;        // m16 tile index (2)
    const int wn   = wid >> 1;       // n32 half index (2)
    const int n0   = blockIdx.x * BN;
    const int m0   = blockIdx.y * BM;

    // global bases for this step
    const __nv_bfloat16* Ahi0 = g_hhi + (size_t)parity * BATCH * DH;
    const __nv_bfloat16* Alo0 = g_hlo + (size_t)parity * BATCH * DH;
    const __nv_bfloat16* Xhi0 = g_xhi + (size_t)t * BATCH * DIN;
    const __nv_bfloat16* Xlo0 = g_xlo + (size_t)t * BATCH * DIN;

    // cp.async per-thread slots
    const int ar = tid >> 3;             // used with +16 for second A op unit
    const int ag = tid & 7;

    auto load_chunk = [&](int cn, int sn) {
        const u32 st = sb + sn * STG;
        const int ko = (cn & 15) * KC;   // element offset within h or x
        const __nv_bfloat16 *pa, *pl;
        if (cn < 16) { pa = Ahi0; pl = Alo0; } else { pa = Xhi0; pl = Xlo0; }
        // A: 32 rows x 8 groups = 256 ops (2/thread per buffer)
        #pragma unroll
        for (int u = 0; u < 2; u++) {
            int r = ar + u * 16, g = ag;
            u32 so = (u32)(r * 128 + ((g ^ (r & 7)) * 16));
            const size_t go = (size_t)(m0 + r) * DH + ko + g * 8;
            CP16(st + OFF_AHI + so, pa + go);
            CP16(st + OFF_ALO + so, pl + go);
        }
        // W: 64 rows x 8 groups = 512 ops (4/thread per buffer)
        #pragma unroll
        for (int u = 0; u < 4; u++) {
            int r = ar + u * 16, g = ag;
            u32 so = (u32)(r * 128 + ((g ^ (r & 7)) * 16));
            const size_t go = (size_t)(n0 + r) * KTOT + cn * KC + g * 8;
            CP16(st + OFF_WHI + so, g_whi + go);
            CP16(st + OFF_WLO + so, g_wlo + go);
        }
        CP_COMMIT();
    };

    // accumulators: 4 n8-tiles x 4 floats
    float acc[16];
    #pragma unroll
    for (int i = 0; i < 16; i++) acc[i] = 0.0f;

    // ldmatrix lane-address components (constant per thread)
    const int aRow = wm * 16 + (lane & 15);
    const int aHi  = (lane >> 4);                    // k-half selector
    const int bRow0 = wn * 32 + (lane & 7) + ((lane >> 4) & 1) * 8;
    const int bHi  = (lane >> 3) & 1;

    // prologue
    #pragma unroll
    for (int p = 0; p < S - 1; p++) load_chunk(p, p);

    for (int c = 0; c < NCH; c++) {
        const int sc = c & (S - 1);
        if (c < NCH - 2)      asm volatile("cp.async.wait_group 2;" ::: "memory");
        else if (c == NCH - 2) asm volatile("cp.async.wait_group 1;" ::: "memory");
        else                   asm volatile("cp.async.wait_group 0;" ::: "memory");
        __syncthreads();

        const u32 st = sb + sc * STG;
        #pragma unroll
        for (int j = 0; j < 4; j++) {      // 4 k16 steps per chunk
            u32 ah[4], al[4], bh[8], bl[8];
            {   // A fragments (hi & lo)
                int g = j * 2 + aHi;
                u32 so = (u32)(aRow * 128 + ((g ^ (aRow & 7)) * 16));
                ldsm4(st + OFF_AHI + so, ah[0], ah[1], ah[2], ah[3]);
                ldsm4(st + OFF_ALO + so, al[0], al[1], al[2], al[3]);
            }
            #pragma unroll
            for (int q = 0; q < 2; q++) {  // two n16 halves -> 4 n8 tiles
                int r = bRow0 + q * 16;
                int g = j * 2 + bHi;
                u32 so = (u32)(r * 128 + ((g ^ (r & 7)) * 16));
                ldsm4(st + OFF_WHI + so, bh[q*4+0], bh[q*4+1], bh[q*4+2], bh[q*4+3]);
                ldsm4(st + OFF_WLO + so, bl[q*4+0], bl[q*4+1], bl[q*4+2], bl[q*4+3]);
            }
            #pragma unroll
            for (int nt = 0; nt < 4; nt++) {
                float* cc = acc + nt * 4;
                mma16816(cc, ah, bh[nt*2+0], bh[nt*2+1]);   // hi*hi
                mma16816(cc, al, bh[nt*2+0], bh[nt*2+1]);   // lo*hi
                mma16816(cc, ah, bl[nt*2+0], bl[nt*2+1]);   // hi*lo
            }
        }
        __syncthreads();

        const int cn = c + S - 1;
        if (cn < NCH) load_chunk(cn, cn & (S - 1));
    }

    // epilogue: bias + tanh; write fp32 out and bf16 hi/lo state (parity^1)
    __nv_bfloat16* hh0 = g_hhi + (size_t)(parity ^ 1) * BATCH * DH;
    __nv_bfloat16* hl0 = g_hlo + (size_t)(parity ^ 1) * BATCH * DH;
    const int rL = lane >> 2, cL = (lane & 3) * 2;
    #pragma unroll
    for (int nt = 0; nt < 4; nt++) {
        const int col = n0 + wn * 32 + nt * 8 + cL;
        const float b0 = __ldg(bias + col), b1 = __ldg(bias + col + 1);
        #pragma unroll
        for (int hf = 0; hf < 2; hf++) {
            const int row = m0 + wm * 16 + rL + hf * 8;
            float z0 = acc[nt * 4 + hf * 2 + 0] + b0;
            float z1 = acc[nt * 4 + hf * 2 + 1] + b1;
            float e0 = __expf(2.0f * z0), e1 = __expf(2.0f * z1);
            float h0 = 1.0f - 2.0f / (e0 + 1.0f);
            float h1 = 1.0f - 2.0f / (e1 + 1.0f);
            *(float2*)(outNext + (size_t)row * DH + col) = make_float2(h0, h1);
            __nv_bfloat16 p0 = __float2bfloat16(h0), p1 = __float2bfloat16(h1);
            __nv_bfloat162 hi2; hi2.x = p0; hi2.y = p1;
            __nv_bfloat162 lo2;
            lo2.x = __float2bfloat16(h0 - __bfloat162float(p0));
            lo2.y = __float2bfloat16(h1 - __bfloat162float(p1));
            *(__nv_bfloat162*)(hh0 + (size_t)row * DH + col) = hi2;
            *(__nv_bfloat162*)(hl0 + (size_t)row * DH + col) = lo2;
        }
    }
}

extern "C" void kernel_launch(void* const* d_in, const int* in_sizes, int n_in,
                              void* d_out, int out_size) {
    const float* seq = (const float*)d_in[0];   // (T, B, DIN)
    const float* W   = (const float*)d_in[1];   // (DH, KTOT)
    const float* b   = (const float*)d_in[2];   // (DH,)
    float* out = (float*)d_out;                 // (T+1, B, DH)
    (void)in_sizes; (void)n_in; (void)out_size;

    cudaFuncSetAttribute(rnn_step, cudaFuncAttributeMaxDynamicSharedMemorySize,
                         SMEM_BYTES);

    const size_t slice = (size_t)BATCH * DH;

    split_w<<<(DH * KTOT) / 256, 256>>>(W);
    split_x<<<(TSTEPS * BATCH * DIN) / 256, 256>>>(seq);
    init_h<<<(BATCH * DH) / 256, 256>>>(out);

    dim3 grid(DH / BN, BATCH / BM);             // (16, 8) = 128 CTAs
    for (int t = 0; t < TSTEPS; t++) {
        rnn_step<<<grid, 128, SMEM_BYTES>>>(b, out + (t + 1) * slice, t, t & 1);
    }
}